// round 1
// baseline (speedup 1.0000x reference)
#include <cuda_runtime.h>
#include <math.h>

#define B_ 32
#define NN 511
#define F_ 512
#define F3 1536

// ---------------- scratch (static device globals; no runtime alloc) ----------------
static __device__ __align__(16) float g_enode[B_ * F_];
static __device__ __align__(16) float g_eforw[B_ * F_];
static __device__ __align__(16) float g_scores[B_ * 512];
static __device__ __align__(16) float g_feat2[(size_t)B_ * NN * F_];
static __device__ __align__(16) float g_fe_iou[(size_t)B_ * NN * F3];
static __device__ __align__(16) float g_ff[(size_t)B_ * 255 * F_];
static __device__ __align__(16) float g_h[(size_t)B_ * NN * F_];
static __device__ __align__(16) float g_c[(size_t)B_ * NN * F_];
static __device__ __align__(16) float g_fc[(size_t)B_ * 256 * F_];
static __device__ __align__(16) float g_iou[(size_t)B_ * 128 * F3];
static __device__ __align__(16) float g_r[B_ * 512];

__device__ __forceinline__ float sigf(float x) { return 1.f / (1.f + expf(-x)); }

// ---------------- e_node / e_forw : out[b,j] = dot(eh[b,:1024], W[j,:1024]) ----------------
__global__ void enode_k(const float* __restrict__ eh,
                        const float* __restrict__ Wn,
                        const float* __restrict__ Wf) {
    int warp = threadIdx.x >> 5, lane = threadIdx.x & 31;
    int j = blockIdx.x * 8 + warp;
    int b = blockIdx.y;
    const float* W = blockIdx.z ? Wf : Wn;
    float* o = blockIdx.z ? g_eforw : g_enode;
    const float4* wr = (const float4*)(W + (size_t)j * 1024);
    const float4* er = (const float4*)(eh + (size_t)b * 1024);
    float s = 0.f;
    for (int t = lane; t < 256; t += 32) {
        float4 w = wr[t], e = er[t];
        s += w.x * e.x + w.y * e.y + w.z * e.z + w.w * e.w;
    }
    #pragma unroll
    for (int off = 16; off; off >>= 1) s += __shfl_xor_sync(0xffffffffu, s, off);
    if (!lane) o[b * F_ + j] = s;
}

// ---------------- scores[b,i] = dot(feat[b,i,:], e_node[b,:]) ----------------
__global__ void scores_k(const float* __restrict__ feat) {
    int gw = (blockIdx.x * blockDim.x + threadIdx.x) >> 5;
    int lane = threadIdx.x & 31;
    if (gw >= B_ * NN) return;
    int b = gw / NN, i = gw - b * NN;
    const float4* fr = (const float4*)(feat + (size_t)gw * F_);
    const float4* er = (const float4*)(g_enode + b * F_);
    float s = 0.f;
    for (int t = lane; t < 128; t += 32) {
        float4 f = fr[t], e = er[t];
        s += f.x * e.x + f.y * e.y + f.z * e.z + f.w * e.w;
    }
    #pragma unroll
    for (int off = 16; off; off >>= 1) s += __shfl_xor_sync(0xffffffffu, s, off);
    if (!lane) g_scores[b * 512 + i] = s;
}

// ---------------- feat2[b,i,:] = softmax over window [i, min(i+3,510)] @ feat ----------------
__global__ void feat2_k(const float* __restrict__ feat) {
    int i = blockIdx.x, b = blockIdx.y;
    int end = min(i + 3, NN - 1), cnt = end - i + 1;
    float sc[4];
    float mx = -1e30f;
    for (int k = 0; k < cnt; k++) { sc[k] = g_scores[b * 512 + i + k]; mx = fmaxf(mx, sc[k]); }
    float sum = 0.f;
    for (int k = 0; k < cnt; k++) { sc[k] = expf(sc[k] - mx); sum += sc[k]; }
    float inv = 1.f / sum;
    size_t base = ((size_t)b * NN + i) * F_;
    for (int f = threadIdx.x; f < F_; f += blockDim.x) {
        float a = 0.f;
        for (int k = 0; k < cnt; k++) a += sc[k] * feat[base + (size_t)k * F_ + f];
        g_feat2[base + f] = a * inv;
    }
}

// ---------------- templated SGEMM: C = A @ W^T (+ mode-specific epilogue) ----------------
// MODE 0: fe_iou = feat2 @ W_fe_iou^T + bias          (M=32*511, N=1536)
// MODE 1: ff     = feat2[parents] @ W_fe_f^T + bias   (M=32*255, N=512)
// MODE 2: fc     = sigmoid(h[child] @ W_f^T + ff[parent]) * c[child]   (level, N=512)
// MODE 3: iou    = (h[c0]+h[c1]) @ W_iou^T + fe_iou[parent]            (level, N=1536)
template <int MODE>
__global__ void gemm_k(const float* __restrict__ W,
                       const float* __restrict__ bias,
                       int M, int N, int s, int np) {
    __shared__ __align__(16) float As[16][68];
    __shared__ __align__(16) float Ws[16][68];
    const int t = threadIdx.x;
    const int tx = t & 15, ty = t >> 4;
    const int bm = blockIdx.y * 64, bn = blockIdx.x * 64;
    const int lr = t >> 2, lk = (t & 3) * 4;

    int row = bm + lr;
    bool aok = row < M;
    const float* ap = g_feat2;  // dummy init
    const float* ap2 = nullptr;
    if (aok) {
        if (MODE == 0) {
            ap = g_feat2 + (size_t)row * F_;
        } else if (MODE == 1) {
            int b = row / 255, p = row - b * 255;
            ap = g_feat2 + ((size_t)b * NN + p) * F_;
        } else if (MODE == 2) {
            int two = 2 * np;
            int b = row / two, cl = row - b * two;
            ap = g_h + ((size_t)b * NN + 2 * s + 1 + cl) * F_;
        } else {
            int b = row / np, pl = row - b * np;
            int p = s + pl;
            ap = g_h + ((size_t)b * NN + 2 * p + 1) * F_;
            ap2 = ap + F_;
        }
    }
    const float* wp = W + (size_t)(bn + lr) * F_;

    float acc[4][4] = {};
    for (int k0 = 0; k0 < 512; k0 += 16) {
        float4 av = make_float4(0.f, 0.f, 0.f, 0.f);
        if (aok) {
            av = *(const float4*)(ap + k0 + lk);
            if (MODE == 3) {
                float4 a2 = *(const float4*)(ap2 + k0 + lk);
                av.x += a2.x; av.y += a2.y; av.z += a2.z; av.w += a2.w;
            }
        }
        float4 wv = *(const float4*)(wp + k0 + lk);
        __syncthreads();
        As[lk + 0][lr] = av.x; As[lk + 1][lr] = av.y; As[lk + 2][lr] = av.z; As[lk + 3][lr] = av.w;
        Ws[lk + 0][lr] = wv.x; Ws[lk + 1][lr] = wv.y; Ws[lk + 2][lr] = wv.z; Ws[lk + 3][lr] = wv.w;
        __syncthreads();
        #pragma unroll
        for (int k = 0; k < 16; k++) {
            float4 a = *(const float4*)&As[k][ty * 4];
            float4 w = *(const float4*)&Ws[k][tx * 4];
            acc[0][0] += a.x * w.x; acc[0][1] += a.x * w.y; acc[0][2] += a.x * w.z; acc[0][3] += a.x * w.w;
            acc[1][0] += a.y * w.x; acc[1][1] += a.y * w.y; acc[1][2] += a.y * w.z; acc[1][3] += a.y * w.w;
            acc[2][0] += a.z * w.x; acc[2][1] += a.z * w.y; acc[2][2] += a.z * w.z; acc[2][3] += a.z * w.w;
            acc[3][0] += a.w * w.x; acc[3][1] += a.w * w.y; acc[3][2] += a.w * w.z; acc[3][3] += a.w * w.w;
        }
    }

    #pragma unroll
    for (int i2 = 0; i2 < 4; i2++) {
        int m = bm + ty * 4 + i2;
        if (m < M) {
            #pragma unroll
            for (int j = 0; j < 4; j++) {
                int n = bn + tx * 4 + j;
                float v = acc[i2][j];
                if (MODE == 0) {
                    g_fe_iou[(size_t)m * F3 + n] = v + bias[n];
                } else if (MODE == 1) {
                    g_ff[(size_t)m * F_ + n] = v + bias[n];
                } else if (MODE == 2) {
                    int two = 2 * np;
                    int b = m / two, cl = m - b * two;
                    int node = 2 * s + 1 + cl, p = s + (cl >> 1);
                    float x = v + g_ff[((size_t)b * 255 + p) * F_ + n];
                    g_fc[(size_t)m * F_ + n] =
                        sigf(x) * g_c[((size_t)b * NN + node) * F_ + n];
                } else {
                    int b = m / np, pl = m - b * np;
                    int p = s + pl;
                    g_iou[(size_t)m * F3 + n] = v + g_fe_iou[((size_t)b * NN + p) * F3 + n];
                }
            }
        }
    }
}

// ---------------- gates ----------------
__global__ void leafgate_k() {
    int idx = blockIdx.x * blockDim.x + threadIdx.x;  // 32*256*512
    int f = idx & 511;
    int r = idx >> 9;           // b*256 + l
    int b = r >> 8, l = r & 255;
    int node = 255 + l;
    size_t io = ((size_t)b * NN + node) * F3;
    float ig = g_fe_iou[io + f];
    float og = g_fe_iou[io + 512 + f];
    float ug = g_fe_iou[io + 1024 + f];
    float cn = sigf(ig) * fmaxf(ug, 0.f);
    float hn = sigf(og) * tanhf(cn);
    size_t ho = ((size_t)b * NN + node) * F_ + f;
    g_c[ho] = cn;
    g_h[ho] = hn;
}

__global__ void gate_k(int s, int np, int total) {
    int idx = blockIdx.x * blockDim.x + threadIdx.x;
    if (idx >= total) return;
    int f = idx & 511;
    int r = idx >> 9;           // b*np + pl
    int b = r / np, pl = r - b * np;
    int node = s + pl;
    size_t io = (size_t)r * F3;
    float ig = g_iou[io + f];
    float og = g_iou[io + 512 + f];
    float ug = g_iou[io + 1024 + f];
    float csum = g_fc[(size_t)(2 * r) * F_ + f] + g_fc[(size_t)(2 * r + 1) * F_ + f];
    float cn = sigf(ig) * fmaxf(ug, 0.f) + csum;
    float hn = sigf(og) * tanhf(cn);
    size_t ho = ((size_t)b * NN + node) * F_ + f;
    g_c[ho] = cn;
    g_h[ho] = hn;
}

// ---------------- final attention readout ----------------
__global__ void rscore_k() {
    int gw = (blockIdx.x * blockDim.x + threadIdx.x) >> 5;
    int lane = threadIdx.x & 31;
    if (gw >= B_ * NN) return;
    int b = gw / NN, i = gw - b * NN;
    const float4* hp = (const float4*)(g_h + (size_t)gw * F_);
    const float4* ep = (const float4*)(g_eforw + b * F_);
    float s = 0.f;
    for (int t = lane; t < 128; t += 32) {
        float4 h = hp[t], e = ep[t];
        s += h.x * e.x + h.y * e.y + h.z * e.z + h.w * e.w;
    }
    #pragma unroll
    for (int off = 16; off; off >>= 1) s += __shfl_xor_sync(0xffffffffu, s, off);
    if (!lane) g_r[b * 512 + i] = s;
}

__global__ void final_k(float* __restrict__ out) {
    __shared__ float red[128];
    __shared__ float pr[NN];
    int b = blockIdx.y, tid = threadIdx.x;
    float mx = -1e30f;
    for (int i = tid; i < NN; i += 128) mx = fmaxf(mx, g_r[b * 512 + i]);
    red[tid] = mx;
    __syncthreads();
    for (int o = 64; o; o >>= 1) {
        if (tid < o) red[tid] = fmaxf(red[tid], red[tid + o]);
        __syncthreads();
    }
    mx = red[0];
    __syncthreads();
    float sm = 0.f;
    for (int i = tid; i < NN; i += 128) {
        float e = expf(g_r[b * 512 + i] - mx);
        pr[i] = e;
        sm += e;
    }
    red[tid] = sm;
    __syncthreads();
    for (int o = 64; o; o >>= 1) {
        if (tid < o) red[tid] += red[tid + o];
        __syncthreads();
    }
    float inv = 1.f / red[0];
    __syncthreads();
    int f = blockIdx.x * 128 + tid;
    float acc = 0.f;
    for (int i = 0; i < NN; i++) acc += pr[i] * g_h[((size_t)b * NN + i) * F_ + f];
    out[b * F_ + f] = acc * inv;
}

// ---------------- launcher ----------------
extern "C" void kernel_launch(void* const* d_in, const int* in_sizes, int n_in,
                              void* d_out, int out_size) {
    const float* feat     = (const float*)d_in[0];
    const float* eh       = (const float*)d_in[5];
    const float* Wn       = (const float*)d_in[6];
    const float* Wf       = (const float*)d_in[7];
    const float* W_iou    = (const float*)d_in[8];
    const float* W_fe_iou = (const float*)d_in[9];
    const float* b_fe_iou = (const float*)d_in[10];
    const float* W_f      = (const float*)d_in[11];
    const float* W_fe_f   = (const float*)d_in[12];
    const float* b_fe_f   = (const float*)d_in[13];
    float* out = (float*)d_out;

    enode_k<<<dim3(64, 32, 2), 256>>>(eh, Wn, Wf);
    scores_k<<<2044, 256>>>(feat);
    feat2_k<<<dim3(NN, B_), 256>>>(feat);

    // fe_iou for all nodes: M = 32*511 = 16352, N = 1536
    gemm_k<0><<<dim3(F3 / 64, (16352 + 63) / 64), 256>>>(W_fe_iou, b_fe_iou, 16352, F3, 0, 0);
    // ff for all parents: M = 32*255 = 8160, N = 512
    gemm_k<1><<<dim3(F_ / 64, (8160 + 63) / 64), 256>>>(W_fe_f, b_fe_f, 8160, F_, 0, 0);

    // level 0: leaves (nodes 255..510)
    leafgate_k<<<(B_ * 256 * F_) / 256, 256>>>();

    // levels 1..8 (bottom-up)
    for (int n = 1; n <= 8; n++) {
        int np = 1 << (8 - n);
        int s = np - 1;
        int Mf = B_ * 2 * np;   // children rows
        int Mi = B_ * np;       // parent rows
        gemm_k<2><<<dim3(F_ / 64, (Mf + 63) / 64), 256>>>(W_f, nullptr, Mf, F_, s, np);
        gemm_k<3><<<dim3(F3 / 64, (Mi + 63) / 64), 256>>>(W_iou, nullptr, Mi, F3, s, np);
        int total = Mi * F_;
        gate_k<<<(total + 255) / 256, 256>>>(s, np, total);
    }

    rscore_k<<<2044, 256>>>();
    final_k<<<dim3(4, B_), 128>>>(out);
}